// round 7
// baseline (speedup 1.0000x reference)
#include <cuda_runtime.h>
#include <math.h>

#define B 16384
#define T 32
#define D 64
#define S 16

// ---- output layout (float32) ----
// reads: (T, B, 128)  at 0
// mem_f: (B, S, 128)  at 67108864
// ptr_f: (B, S)       at 100663296
// active_slots scalar at 100925440
#define READS_OFF 0
#define MEM_OFF   67108864
#define PTR_OFF   100663296
#define ACT_OFF   100925440

// ---- device scratch ----
__device__ float g_ZF[B * T * 128];   // rope'd z_flat rows
__device__ float g_QZ[B * T * 128];   // f_q(z_flat)
__device__ float g_KZ[B * T * 128];
__device__ float g_VZ[B * T * 128];
__device__ float g_Q0[B * S * 128];   // f_q(mem0 rows)
__device__ float g_K0[B * S * 128];
__device__ float g_V0[B * S * 128];
__device__ int   g_count;

// ================= phase 1: batched transform GEMMs =================
#define CH 16
#define NROW_Z   (B * T)                  // 524288
#define NCHUNK_Z (NROW_Z / CH)            // 32768
#define NCHUNK   ((NROW_Z + B * S) / CH)  // 49152
#define WST 68                            // multiple of 4 -> float4-aligned rows
#define SW_MAT (64 * WST)
#define P1_SMEM_FLOATS (6 * SW_MAT + CH * 128 + 2048)
#define P1_SMEM_BYTES  (P1_SMEM_FLOATS * 4)

__device__ __forceinline__ void fma4(float4& a, const float4 w, const float s) {
    a.x = fmaf(w.x, s, a.x); a.y = fmaf(w.y, s, a.y);
    a.z = fmaf(w.z, s, a.z); a.w = fmaf(w.w, s, a.w);
}

__global__ void __launch_bounds__(256) phase1_kernel(
    const float* __restrict__ zr, const float* __restrict__ zi,
    const float* __restrict__ mem0,
    const float* __restrict__ Wqr, const float* __restrict__ Wqi,
    const float* __restrict__ Wkr, const float* __restrict__ Wki,
    const float* __restrict__ Wvr, const float* __restrict__ Wvi)
{
    extern __shared__ float sm[];
    float* sW  = sm;                    // 6 * SW_MAT, transposed: sW[m][d*WST+e] = W_m[e][d]
    float* sX  = sm + 6 * SW_MAT;       // CH * 128 staged rows
    float* sCs = sX + CH * 128;         // 32 x 32 cos table
    float* sSn = sCs + 1024;            // 32 x 32 sin table

    {
        const float* Ws[6] = {Wqr, Wqi, Wkr, Wki, Wvr, Wvi};
        for (int k = threadIdx.x; k < 6 * 4096; k += 256) {
            int m = k >> 12, r = k & 4095, e = r >> 6, d = r & 63;
            sW[m * SW_MAT + d * WST + e] = Ws[m][r];
        }
        for (int k = threadIdx.x; k < 1024; k += 256) {
            int t = k >> 5, dm = k & 31;
            float freq = exp2f(-0.41524101186092f * (float)dm); // 10000^(-dm/32)
            float ang = (float)t * freq;
            sincosf(ang, &sSn[k], &sCs[k]);
        }
    }
    __syncthreads();

    const int lane = threadIdx.x & 31;
    const int warp = threadIdx.x >> 5;
    const int half = warp & 1;                 // 0: real output half, 1: imag
    const int e4   = (lane & 15) * 4;          // column within 64-wide half
    const int r0   = ((warp >> 1) << 1) | (lane >> 4);  // rows r0, r0+8
    const float sgn = half ? 1.0f : -1.0f;

    const float* sWqr = sW;
    const float* sWqi = sW + 1 * SW_MAT;
    const float* sWkr = sW + 2 * SW_MAT;
    const float* sWki = sW + 3 * SW_MAT;
    const float* sWvr = sW + 4 * SW_MAT;
    const float* sWvi = sW + 5 * SW_MAT;

    for (int ch = blockIdx.x; ch < NCHUNK; ch += gridDim.x) {
        if (ch < NCHUNK_Z) {
            int rowbase = ch * CH;
            for (int k = threadIdx.x; k < CH * 64; k += 256) {
                int i = k >> 6, d = k & 63;
                int row = rowbase + i;
                float a  = zr[row * 64 + d];
                float bb = zi[row * 64 + d];
                int t = row & 31;
                float cs = sCs[t * 32 + (d & 31)];
                float sn = sSn[t * 32 + (d & 31)];
                float xr = a * cs - bb * sn;
                float xi = a * sn + bb * cs;
                sX[i * 128 + d]      = xr;
                sX[i * 128 + 64 + d] = xi;
                g_ZF[row * 128 + d]      = xr;
                g_ZF[row * 128 + 64 + d] = xi;
            }
        } else {
            int rowbase = (ch - NCHUNK_Z) * CH;
            for (int k = threadIdx.x; k < CH * 128; k += 256) {
                int i = k >> 7, d = k & 127;
                sX[i * 128 + d] = mem0[(rowbase + i) * 128 + d];
            }
        }
        __syncthreads();

        float4 z4 = {0.f, 0.f, 0.f, 0.f};
        float4 aq0 = z4, aq1 = z4, ak0 = z4, ak1 = z4, av0 = z4, av1 = z4;
        const float* x0 = sX + r0 * 128;
        const float* x1 = sX + (r0 + 8) * 128;
        const float* xA0 = half ? (x0 + 64) : x0;   // multiplies W_r
        const float* xB0 = half ? x0 : (x0 + 64);   // multiplies sgn*W_i
        const float* xA1 = half ? (x1 + 64) : x1;
        const float* xB1 = half ? x1 : (x1 + 64);

        #pragma unroll 4
        for (int d = 0; d < 64; d++) {
            float4 wqr = *(const float4*)(sWqr + d * WST + e4);
            float4 wqi = *(const float4*)(sWqi + d * WST + e4);
            float4 wkr = *(const float4*)(sWkr + d * WST + e4);
            float4 wki = *(const float4*)(sWki + d * WST + e4);
            float4 wvr = *(const float4*)(sWvr + d * WST + e4);
            float4 wvi = *(const float4*)(sWvi + d * WST + e4);
            float p0 = xA0[d];
            float q0 = sgn * xB0[d];
            float p1 = xA1[d];
            float q1 = sgn * xB1[d];
            fma4(aq0, wqr, p0); fma4(aq0, wqi, q0);
            fma4(ak0, wkr, p0); fma4(ak0, wki, q0);
            fma4(av0, wvr, p0); fma4(av0, wvi, q0);
            fma4(aq1, wqr, p1); fma4(aq1, wqi, q1);
            fma4(ak1, wkr, p1); fma4(ak1, wki, q1);
            fma4(av1, wvr, p1); fma4(av1, wvi, q1);
        }

        int eo = e4 + half * 64;
        if (ch < NCHUNK_Z) {
            int ra = ch * CH + r0, rb = ra + 8;
            *(float4*)(g_QZ + ra * 128 + eo) = aq0;
            *(float4*)(g_KZ + ra * 128 + eo) = ak0;
            *(float4*)(g_VZ + ra * 128 + eo) = av0;
            *(float4*)(g_QZ + rb * 128 + eo) = aq1;
            *(float4*)(g_KZ + rb * 128 + eo) = ak1;
            *(float4*)(g_VZ + rb * 128 + eo) = av1;
        } else {
            int ra = (ch - NCHUNK_Z) * CH + r0, rb = ra + 8;
            *(float4*)(g_Q0 + ra * 128 + eo) = aq0;
            *(float4*)(g_K0 + ra * 128 + eo) = ak0;
            *(float4*)(g_V0 + ra * 128 + eo) = av0;
            *(float4*)(g_Q0 + rb * 128 + eo) = aq1;
            *(float4*)(g_K0 + rb * 128 + eo) = ak1;
            *(float4*)(g_V0 + rb * 128 + eo) = av1;
        }
        __syncthreads();
    }
}

// ================= phase 2: per-batch recurrence =================
__global__ void __launch_bounds__(128) phase2_kernel(
    const float* __restrict__ ctrl, const float* __restrict__ mem0,
    const float* __restrict__ ptr0, float* __restrict__ out)
{
    const int b = blockIdx.x;
    const int j = threadIdx.x;

    __shared__ __align__(16) float Qs[16][132];
    __shared__ __align__(16) float Ks[16][132];
    __shared__ float As[16][17];
    __shared__ float wS[16];
    __shared__ float ptrS[16];
    __shared__ float nptrS[16];

    float Qc[16], Kc[16], Vc[16], Mc[16];
    #pragma unroll
    for (int s = 0; s < 16; s++) {
        int idx = (b * 16 + s) * 128 + j;
        Qc[s] = g_Q0[idx];
        Kc[s] = g_K0[idx];
        Vc[s] = g_V0[idx];
        Mc[s] = mem0[idx];
    }
    if (j < 16) ptrS[j] = ptr0[b * 16 + j];
    __syncthreads();

    const int s_row = j >> 3;
    const int u0 = (j & 7) * 2;

    for (int t = 0; t < 32; t++) {
        int base = (b * 32 + t) * 128 + j;
        float qz = g_QZ[base];
        float kz = g_KZ[base];
        float vz = g_VZ[base];
        float zf = g_ZF[base];

        int cb = (b * 32 + t) * 3;
        float g0 = 1.0f / (1.0f + __expf(-ctrl[cb + 0]));
        float g1 = 1.0f / (1.0f + __expf(-ctrl[cb + 1]));
        float g2 = 1.0f / (1.0f + __expf(-ctrl[cb + 2]));
        float tot = g0 + g1 + g2 + 1e-6f;
        float push = g0 / tot, pop = g1 / tot, stay = g2 / tot;

        #pragma unroll
        for (int s = 0; s < 16; s++) {
            Qc[s] = fmaf(push, qz - Qc[s], Qc[s]);
            Kc[s] = fmaf(push, kz - Kc[s], Kc[s]);
            Vc[s] = fmaf(push, vz - Vc[s], Vc[s]);
            Mc[s] = fmaf(push, zf - Mc[s], Mc[s]);
            Qs[s][j] = Qc[s];
            Ks[s][j] = Kc[s];
        }
        if (j < 16) {
            float pm = ptrS[(j + 15) & 15];
            float pp = ptrS[(j + 1) & 15];
            nptrS[j] = push * pm + pop * pp + stay * ptrS[j];
        }
        __syncthreads();   // #1: Q/K staged, nptr ready

        // logits A[s_row][u0], A[s_row][u0+1]
        float a0 = 0.f, a1 = 0.f;
        const float4* qrow  = (const float4*)(&Qs[s_row][0]);
        const float4* k0row = (const float4*)(&Ks[u0][0]);
        const float4* k1row = (const float4*)(&Ks[u0 + 1][0]);
        #pragma unroll 8
        for (int c = 0; c < 32; c++) {
            float4 q  = qrow[c];
            float4 ka = k0row[c];
            float4 kb = k1row[c];
            a0 = fmaf(q.x, ka.x, a0); a0 = fmaf(q.y, ka.y, a0);
            a0 = fmaf(q.z, ka.z, a0); a0 = fmaf(q.w, ka.w, a0);
            a1 = fmaf(q.x, kb.x, a1); a1 = fmaf(q.y, kb.y, a1);
            a1 = fmaf(q.z, kb.z, a1); a1 = fmaf(q.w, kb.w, a1);
        }
        As[s_row][u0]     = a0 * 0.125f;
        As[s_row][u0 + 1] = a1 * 0.125f;
        __syncthreads();   // #2: logits done

        if (j < 16) {      // softmax of row j (in place)
            float mx = -1e30f;
            #pragma unroll
            for (int u = 0; u < 16; u++) mx = fmaxf(mx, As[j][u]);
            float e[16];
            float sum = 0.f;
            #pragma unroll
            for (int u = 0; u < 16; u++) { e[u] = __expf(As[j][u] - mx); sum += e[u]; }
            float inv = 1.0f / sum;
            #pragma unroll
            for (int u = 0; u < 16; u++) As[j][u] = e[u] * inv;
        }
        __syncthreads();   // #3: attn normalized

        if (j < 16) {      // w[u] = sum_s nptr[s] * attn[s][u]; advance ptr
            float w = 0.f;
            #pragma unroll
            for (int s = 0; s < 16; s++) w = fmaf(nptrS[s], As[s][j], w);
            wS[j] = w;
            ptrS[j] = nptrS[j];
        }
        __syncthreads();   // #4: w ready

        float r = 0.f;
        #pragma unroll
        for (int u = 0; u < 16; u++) r = fmaf(wS[u], Vc[u], r);
        out[READS_OFF + ((size_t)t * B + b) * 128 + j] = r;
    }

    // epilogue: mem_f, ptr_f, active-slot count
    #pragma unroll
    for (int s = 0; s < 16; s++)
        out[MEM_OFF + (size_t)(b * 16 + s) * 128 + j] = Mc[s];
    if (j < 16)
        out[PTR_OFF + b * 16 + j] = ptrS[j];
    if (j < 32) {
        unsigned m = __ballot_sync(0xffffffffu, (j < 16) && (ptrS[j] > 0.1f));
        if (j == 0) atomicAdd(&g_count, __popc(m));
    }
}

__global__ void init_kernel() { g_count = 0; }

__global__ void finalize_kernel(float* __restrict__ out) {
    out[ACT_OFF] = (float)g_count * (1.0f / (float)B);
}

extern "C" void kernel_launch(void* const* d_in, const int* in_sizes, int n_in,
                              void* d_out, int out_size) {
    const float* zr   = (const float*)d_in[0];
    const float* zi   = (const float*)d_in[1];
    const float* ctrl = (const float*)d_in[2];
    const float* mem0 = (const float*)d_in[3];
    const float* ptr0 = (const float*)d_in[4];
    const float* Wqr  = (const float*)d_in[5];
    const float* Wqi  = (const float*)d_in[6];
    const float* Wkr  = (const float*)d_in[7];
    const float* Wki  = (const float*)d_in[8];
    const float* Wvr  = (const float*)d_in[9];
    const float* Wvi  = (const float*)d_in[10];
    float* out = (float*)d_out;

    cudaFuncSetAttribute(phase1_kernel,
                         cudaFuncAttributeMaxDynamicSharedMemorySize,
                         P1_SMEM_BYTES);

    init_kernel<<<1, 1>>>();
    phase1_kernel<<<148, 256, P1_SMEM_BYTES>>>(zr, zi, mem0,
                                               Wqr, Wqi, Wkr, Wki, Wvr, Wvi);
    phase2_kernel<<<B, 128>>>(ctrl, mem0, ptr0, out);
    finalize_kernel<<<1, 1>>>(out);
}

// round 9
// speedup vs baseline: 3.0352x; 3.0352x over previous
#include <cuda_runtime.h>
#include <math.h>

#define B 16384
#define T 32
#define S 16

#define READS_OFF 0
#define MEM_OFF   67108864
#define PTR_OFF   100663296
#define ACT_OFF   100925440

__device__ float g_ZF[B * T * 128];
__device__ float g_VZ[B * T * 128];
__device__ float g_KT[B * S * 128];
__device__ float g_V0[B * S * 128];
__device__ float g_G0[B * S * S];
__device__ float g_H[128 * 128];
__device__ int   g_count;

__device__ __forceinline__ void fma4(float4& a, const float4 w, const float s) {
    a.x = fmaf(w.x, s, a.x); a.y = fmaf(w.y, s, a.y);
    a.z = fmaf(w.z, s, a.z); a.w = fmaf(w.w, s, a.w);
}
__device__ __forceinline__ void fma4n(float4& a, const float4 w, const float s) {
    a.x = fmaf(w.x, -s, a.x); a.y = fmaf(w.y, -s, a.y);
    a.z = fmaf(w.z, -s, a.z); a.w = fmaf(w.w, -s, a.w);
}
// M[e][a] for M = [[Wr, -Wi],[Wi, Wr]]
__device__ __forceinline__ float cmat(const float* Wr, const float* Wi, int e, int a) {
    if (e < 64) return (a < 64) ? Wr[e * 64 + a] : -Wi[e * 64 + (a - 64)];
    else        return (a < 64) ? Wi[(e - 64) * 64 + a] : Wr[(e - 64) * 64 + (a - 64)];
}

// ---------- H = Mq^T Mk ----------
__global__ void hprep_kernel(const float* __restrict__ Wqr, const float* __restrict__ Wqi,
                             const float* __restrict__ Wkr, const float* __restrict__ Wki) {
    int a = blockIdx.x, bb = threadIdx.x;
    float s = 0.f;
    for (int e = 0; e < 128; e++)
        s = fmaf(cmat(Wqr, Wqi, e, a), cmat(Wkr, Wki, e, bb), s);
    g_H[a * 128 + bb] = s;
    if (a == 0 && bb == 0) g_count = 0;
}

// ---------- phase1z: ZF = rope(z), VZ = Mv * ZF ----------
#define WST 68
#define Z_SMEM_BYTES ((2 * 64 * WST + 32 * 128 + 2048) * 4)
__global__ void __launch_bounds__(256) phase1z_kernel(
    const float* __restrict__ zr, const float* __restrict__ zi,
    const float* __restrict__ Wvr, const float* __restrict__ Wvi)
{
    extern __shared__ float sm[];
    float* sWr = sm;                  // [64][WST] : sWr[d*WST+e] = Wvr[e][d]
    float* sWi = sm + 64 * WST;
    float* sX  = sm + 2 * 64 * WST;   // [32][128]
    float* sCs = sX + 32 * 128;
    float* sSn = sCs + 1024;

    for (int k = threadIdx.x; k < 4096; k += 256) {
        int e = k >> 6, d = k & 63;
        sWr[d * WST + e] = Wvr[k];
        sWi[d * WST + e] = Wvi[k];
    }
    for (int k = threadIdx.x; k < 1024; k += 256) {
        int t = k >> 5, dm = k & 31;
        float ang = (float)t * exp2f(-0.41524101186092f * (float)dm);
        sincosf(ang, &sSn[k], &sCs[k]);
    }
    __syncthreads();

    const int lane = threadIdx.x & 31, warp = threadIdx.x >> 5;
    const int half = warp & 1;
    const int e4 = (lane & 15) * 4;
    const int r0 = ((warp >> 1) << 1) | (lane >> 4);   // 0..7

    for (int ch = blockIdx.x; ch < B * T / 32; ch += gridDim.x) {
        int rowbase = ch * 32;
        for (int k = threadIdx.x; k < 32 * 64; k += 256) {
            int i = k >> 6, d = k & 63;
            int row = rowbase + i;
            float a = zr[row * 64 + d], c = zi[row * 64 + d];
            int t = row & 31;
            float cs = sCs[t * 32 + (d & 31)], sn = sSn[t * 32 + (d & 31)];
            float xr = a * cs - c * sn, xi = a * sn + c * cs;
            sX[i * 128 + d] = xr; sX[i * 128 + 64 + d] = xi;
            g_ZF[row * 128 + d] = xr; g_ZF[row * 128 + 64 + d] = xi;
        }
        __syncthreads();

        float4 acc[4];
        #pragma unroll
        for (int q = 0; q < 4; q++) acc[q] = make_float4(0.f, 0.f, 0.f, 0.f);
        #pragma unroll 4
        for (int d = 0; d < 64; d++) {
            float4 wr = *(const float4*)(sWr + d * WST + e4);
            float4 wi = *(const float4*)(sWi + d * WST + e4);
            #pragma unroll
            for (int q = 0; q < 4; q++) {
                const float* x = sX + (r0 + q * 8) * 128;
                float xa = half ? x[64 + d] : x[d];
                float xb = half ? x[d]      : x[64 + d];
                fma4(acc[q], wr, xa);
                if (half) fma4(acc[q], wi, xb); else fma4n(acc[q], wi, xb);
            }
        }
        int eo = e4 + half * 64;
        #pragma unroll
        for (int q = 0; q < 4; q++)
            *(float4*)(g_VZ + (rowbase + r0 + q * 8) * 128 + eo) = acc[q];
        __syncthreads();
    }
}

// ---------- phase1m: per batch: KT0 = H*mem0, V0 = Mv*mem0, G0 = mem0 @ KT0^T ----------
#define MST 132
#define M_SMEM_BYTES ((2 * 128 * MST + 16 * 128 + 16 * MST) * 4)
__global__ void __launch_bounds__(256) phase1m_kernel(
    const float* __restrict__ mem0,
    const float* __restrict__ Wvr, const float* __restrict__ Wvi)
{
    extern __shared__ float sm[];
    float* sH  = sm;                       // [128][MST] : sH[d*MST+e] = H[e][d]
    float* sMv = sm + 128 * MST;           // sMv[d*MST+e] = Mv[e][d]
    float* sX  = sm + 2 * 128 * MST;       // [16][128]
    float* sKT = sX + 16 * 128;            // [16][MST]

    for (int k = threadIdx.x; k < 16384; k += 256) {
        int e = k >> 7, d = k & 127;
        sH[d * MST + e]  = g_H[k];
        sMv[d * MST + e] = cmat(Wvr, Wvi, e, d);
    }
    __syncthreads();

    const int lane = threadIdx.x & 31, warp = threadIdx.x >> 5;
    const int e4 = lane * 4;
    const int r0 = warp * 2;

    for (int bb = blockIdx.x; bb < B; bb += gridDim.x) {
        for (int k = threadIdx.x; k < 16 * 128; k += 256)
            sX[k] = mem0[bb * 2048 + k];
        __syncthreads();

        float4 kt0 = {0.f,0.f,0.f,0.f}, kt1 = kt0, v0 = kt0, v1 = kt0;
        #pragma unroll 4
        for (int d = 0; d < 128; d++) {
            float4 h4 = *(const float4*)(sH + d * MST + e4);
            float4 m4 = *(const float4*)(sMv + d * MST + e4);
            float x0 = sX[r0 * 128 + d], x1 = sX[(r0 + 1) * 128 + d];
            fma4(kt0, h4, x0); fma4(v0, m4, x0);
            fma4(kt1, h4, x1); fma4(v1, m4, x1);
        }
        int gb = (bb * 16 + r0) * 128 + e4;
        *(float4*)(g_KT + gb) = kt0; *(float4*)(g_V0 + gb) = v0;
        *(float4*)(g_KT + gb + 128) = kt1; *(float4*)(g_V0 + gb + 128) = v1;
        *(float4*)(sKT + r0 * MST + e4) = kt0;
        *(float4*)(sKT + (r0 + 1) * MST + e4) = kt1;
        __syncthreads();

        {   // G0[s][u] = sum_e sX[s][e] * sKT[u][e]
            int s = threadIdx.x >> 4, u = threadIdx.x & 15;
            float a = 0.f;
            #pragma unroll 4
            for (int e = 0; e < 128; e++)
                a = fmaf(sX[s * 128 + e], sKT[u * MST + e], a);
            g_G0[bb * 256 + threadIdx.x] = a;
        }
        __syncthreads();
    }
}

// ---------- phase2 ----------
__global__ void __launch_bounds__(128) phase2_kernel(
    const float* __restrict__ ctrl, const float* __restrict__ mem0,
    const float* __restrict__ ptr0, float* __restrict__ out)
{
    const int b = blockIdx.x, j = threadIdx.x;
    __shared__ float KTs[16 * 130];
    __shared__ float G0s[16][17];
    __shared__ float As[16][17];
    __shared__ float RmS[128];
    __shared__ float part[16][8];
    __shared__ float bS[16], wS[16], ptrS[16], nptrS[16];
    __shared__ float pushA[32], popA[32], stayA[32], betaA[32];

    float V0c[16], M0c[16];
    #pragma unroll
    for (int s = 0; s < 16; s++) {
        int idx = (b * 16 + s) * 128 + j;
        V0c[s] = g_V0[idx];
        M0c[s] = mem0[idx];
        KTs[s * 130 + j] = g_KT[idx];
    }
    if (j < 16) ptrS[j] = ptr0[b * 16 + j];
    { int s = j >> 3, u0 = (j & 7) * 2;
      G0s[s][u0]     = g_G0[b * 256 + s * 16 + u0];
      G0s[s][u0 + 1] = g_G0[b * 256 + s * 16 + u0 + 1]; }
    if (j < 32) {
        int cb = (b * 32 + j) * 3;
        float g0 = 1.0f / (1.0f + __expf(-ctrl[cb]));
        float g1 = 1.0f / (1.0f + __expf(-ctrl[cb + 1]));
        float g2 = 1.0f / (1.0f + __expf(-ctrl[cb + 2]));
        float tot = g0 + g1 + g2 + 1e-6f;
        pushA[j] = g0 / tot; popA[j] = g1 / tot; stayA[j] = g2 / tot;
    }
    __syncthreads();
    if (j == 0) {
        float bta = 1.f;
        for (int t = 0; t < 32; t++) { bta *= (1.f - pushA[t]); betaA[t] = bta; }
    }
    __syncthreads();

    const int u_g = j & 15, g_g = j >> 4;
    float Rm = 0.f, Rv = 0.f;

    for (int t = 0; t < 32; t++) {
        float p = pushA[t];
        float beta = betaA[t];
        int base = (b * 32 + t) * 128 + j;
        Rm = fmaf(p, g_ZF[base] - Rm, Rm);
        Rv = fmaf(p, g_VZ[base] - Rv, Rv);
        RmS[j] = Rm;
        if (j < 16) {
            float pm = ptrS[(j + 15) & 15];
            float pp = ptrS[(j + 1) & 15];
            nptrS[j] = p * pm + popA[t] * pp + stayA[t] * ptrS[j];
        }
        __syncthreads();   // 1: RmS, nptr

        {   // partial b: sum over c in [g*16, g*16+16)
            float a = 0.f;
            int c0 = g_g * 16;
            #pragma unroll
            for (int i = 0; i < 16; i++)
                a = fmaf(RmS[c0 + i], KTs[u_g * 130 + c0 + i], a);
            part[u_g][g_g] = a;
        }
        __syncthreads();   // 2: partials

        if (j < 16) {
            float bv = 0.f;
            #pragma unroll
            for (int g = 0; g < 8; g++) bv += part[j][g];
            bS[j] = bv;
        }
        __syncthreads();   // 2b: bS ready (cheap extra barrier)

        if (j < 16) {      // softmax row j
            float c2 = 0.125f * beta;
            float c1 = c2 * beta;
            float l[16], mx = -1e30f;
            #pragma unroll
            for (int u = 0; u < 16; u++) {
                l[u] = fmaf(c1, G0s[j][u], c2 * bS[u]);
                mx = fmaxf(mx, l[u]);
            }
            float sum = 0.f;
            #pragma unroll
            for (int u = 0; u < 16; u++) { l[u] = __expf(l[u] - mx); sum += l[u]; }
            float inv = 1.0f / sum;
            #pragma unroll
            for (int u = 0; u < 16; u++) As[j][u] = l[u] * inv;
        }
        __syncthreads();   // 3: As

        if (j < 16) {
            float w = 0.f;
            #pragma unroll
            for (int s = 0; s < 16; s++) w = fmaf(nptrS[s], As[s][j], w);
            wS[j] = w;
            ptrS[j] = nptrS[j];
        }
        __syncthreads();   // 4: wS

        float acc = 0.f, sw = 0.f;
        #pragma unroll
        for (int u = 0; u < 16; u++) { float w = wS[u]; acc = fmaf(w, V0c[u], acc); sw += w; }
        out[READS_OFF + ((size_t)t * B + b) * 128 + j] = fmaf(beta, acc, sw * Rv);
    }

    float bf = betaA[31];
    #pragma unroll
    for (int s = 0; s < 16; s++)
        out[MEM_OFF + (size_t)(b * 16 + s) * 128 + j] = fmaf(bf, M0c[s], Rm);
    if (j < 16) out[PTR_OFF + b * 16 + j] = ptrS[j];
    if (j < 32) {
        unsigned m = __ballot_sync(0xffffffffu, (j < 16) && (ptrS[j] > 0.1f));
        if (j == 0) atomicAdd(&g_count, __popc(m));
    }
}

__global__ void finalize_kernel(float* __restrict__ out) {
    out[ACT_OFF] = (float)g_count * (1.0f / (float)B);
}

extern "C" void kernel_launch(void* const* d_in, const int* in_sizes, int n_in,
                              void* d_out, int out_size) {
    const float* zr   = (const float*)d_in[0];
    const float* zi   = (const float*)d_in[1];
    const float* ctrl = (const float*)d_in[2];
    const float* mem0 = (const float*)d_in[3];
    const float* ptr0 = (const float*)d_in[4];
    const float* Wqr  = (const float*)d_in[5];
    const float* Wqi  = (const float*)d_in[6];
    const float* Wkr  = (const float*)d_in[7];
    const float* Wki  = (const float*)d_in[8];
    const float* Wvr  = (const float*)d_in[9];
    const float* Wvi  = (const float*)d_in[10];
    float* out = (float*)d_out;

    cudaFuncSetAttribute(phase1z_kernel, cudaFuncAttributeMaxDynamicSharedMemorySize, Z_SMEM_BYTES);
    cudaFuncSetAttribute(phase1m_kernel, cudaFuncAttributeMaxDynamicSharedMemorySize, M_SMEM_BYTES);

    hprep_kernel<<<128, 128>>>(Wqr, Wqi, Wkr, Wki);
    phase1z_kernel<<<444, 256, Z_SMEM_BYTES>>>(zr, zi, Wvr, Wvi);
    phase1m_kernel<<<148, 256, M_SMEM_BYTES>>>(mem0, Wvr, Wvi);
    phase2_kernel<<<B, 128>>>(ctrl, mem0, ptr0, out);
    finalize_kernel<<<1, 1>>>(out);
}